// round 4
// baseline (speedup 1.0000x reference)
#include <cuda_runtime.h>
#include <math_constants.h>

#define NT 512        // threads per CTA (one CTA per row)
#define S_SAMP 4096   // samples for cutoff estimation
#define NC 8192       // max candidates kept per row

__global__ __launch_bounds__(NT, 1)
void sampler_kernel(const float* __restrict__ logits,
                    const float* __restrict__ temps,
                    const int*   __restrict__ topks,
                    const float* __restrict__ topps,
                    const float* __restrict__ minps,
                    const float* __restrict__ noise,
                    float* __restrict__ out, int V)
{
    extern __shared__ unsigned char smem_raw[];
    float* s_vals = (float*)smem_raw;            // NC floats
    int*   s_idxs = (int*)(s_vals + NC);         // NC ints
    float* s_a    = (float*)(s_idxs + NC);       // NC floats (samples, then probs/scan)
    float* s_b    = s_a + NC;                    // NC floats (scan ping-pong)

    __shared__ float rf[NT];
    __shared__ int   ri[NT];
    __shared__ int   sh_cnt;

    const int tid = threadIdx.x;
    const int row = blockIdx.x;
    const float* lg = logits + (size_t)row * V;
    const float* nz = noise  + (size_t)row * V;
    const float T = temps[row];
    int k = topks[row]; if (k < 1) k = 1; if (k > V) k = V;
    const float p  = topps[row];
    const float mp = minps[row];

    // ---------------- pass 0: row max (+ strided samples) ----------------
    float lmax = -CUDART_INF_F;
    const float4* lg4 = (const float4*)lg;
    const int V4 = V >> 2;
    for (int i = tid; i < V4; i += NT) {
        float4 v = lg4[i];
        float a = __fdiv_rn(v.x, T), b = __fdiv_rn(v.y, T);
        float c = __fdiv_rn(v.z, T), d = __fdiv_rn(v.w, T);
        lmax = fmaxf(lmax, fmaxf(fmaxf(a, b), fmaxf(c, d)));
    }
    rf[tid] = lmax; __syncthreads();
    for (int s = NT / 2; s; s >>= 1) { if (tid < s) rf[tid] = fmaxf(rf[tid], rf[tid + s]); __syncthreads(); }
    const float M = rf[0];
    __syncthreads();

    int stride = V / S_SAMP; if (stride < 1) stride = 1;
    for (int s = tid; s < S_SAMP; s += NT) {
        size_t gi = (size_t)s * stride;
        s_a[s] = (gi < (size_t)V) ? __fdiv_rn(lg[gi], T) : -CUDART_INF_F;
    }
    // bitonic sort samples descending (values only)
    for (int size = 2; size <= S_SAMP; size <<= 1)
        for (int st = size >> 1; st; st >>= 1) {
            __syncthreads();
            for (int i = tid; i < S_SAMP; i += NT) {
                int l = i ^ st;
                if (l > i) {
                    float vi = s_a[i], vl = s_a[l];
                    bool dir = ((i & size) == 0);
                    bool sw  = vl > vi;
                    if (sw == dir) { s_a[i] = vl; s_a[l] = vi; }
                }
            }
        }
    __syncthreads();

    // ---------------- choose cutoff, gather candidates ----------------
    int rank = (k + 1800) / stride;
    if (rank > S_SAMP - 1) rank = S_SAMP - 1;
    int n = 0;
    const int lane = tid & 31;
    const unsigned lml = (1u << lane) - 1u;

    for (int attempt = 0; attempt < 6; ++attempt) {
        float cutoff = s_a[rank];
        if (tid == 0) sh_cnt = 0;
        __syncthreads();
        for (int i = tid; i < V4; i += NT) {
            float4 v = lg4[i];
            float xs[4];
            xs[0] = __fdiv_rn(v.x, T); xs[1] = __fdiv_rn(v.y, T);
            xs[2] = __fdiv_rn(v.z, T); xs[3] = __fdiv_rn(v.w, T);
            #pragma unroll
            for (int c = 0; c < 4; ++c) {
                bool hit = xs[c] >= cutoff;
                unsigned mask = __ballot_sync(0xFFFFFFFFu, hit);
                if (mask) {
                    int leader = __ffs(mask) - 1;
                    int base = 0;
                    if (lane == leader) base = atomicAdd(&sh_cnt, __popc(mask));
                    base = __shfl_sync(0xFFFFFFFFu, base, leader);
                    if (hit) {
                        int pos = base + __popc(mask & lml);
                        if (pos < NC) { s_vals[pos] = xs[c]; s_idxs[pos] = (i << 2) + c; }
                    }
                }
            }
        }
        __syncthreads();
        n = sh_cnt;
        __syncthreads();
        if (n >= k && n <= NC) break;
        if (n < k) rank = min(S_SAMP - 1, rank + 256);   // lower cutoff -> more
        else       rank = max(0, rank - 256);            // overflow -> raise cutoff
    }
    if (n > NC) n = NC;
    if (k > n) k = n;   // safety (should never trigger)

    // ---------------- sort candidates desc by (value, index-desc) ----------------
    int NP = 1; while (NP < n) NP <<= 1;
    for (int j = n + tid; j < NP; j += NT) { s_vals[j] = -CUDART_INF_F; s_idxs[j] = -1; }
    __syncthreads();
    for (int size = 2; size <= NP; size <<= 1)
        for (int st = size >> 1; st; st >>= 1) {
            __syncthreads();
            for (int i = tid; i < NP; i += NT) {
                int l = i ^ st;
                if (l > i) {
                    float vi = s_vals[i], vl = s_vals[l];
                    int   ii = s_idxs[i], il = s_idxs[l];
                    bool dir = ((i & size) == 0);
                    bool sw  = (vl > vi) || (vl == vi && il > ii);
                    if (sw == dir) { s_vals[i] = vl; s_vals[l] = vi; s_idxs[i] = il; s_idxs[l] = ii; }
                }
            }
        }
    __syncthreads();

    // ---------------- top-k: threshold and survivor count m ----------------
    const float thr = s_vals[k - 1];
    int c = 0;
    for (int j = tid; j < n; j += NT) c += (s_vals[j] >= thr) ? 1 : 0;
    ri[tid] = c; __syncthreads();
    for (int s = NT / 2; s; s >>= 1) { if (tid < s) ri[tid] += ri[tid + s]; __syncthreads(); }
    const int m = ri[0];
    __syncthreads();

    // ---------------- softmax sum over survivors ----------------
    float z = 0.f;
    for (int j = tid; j < m; j += NT) z += expf(s_vals[j] - M);
    rf[tid] = z; __syncthreads();
    for (int s = NT / 2; s; s >>= 1) { if (tid < s) rf[tid] += rf[tid + s]; __syncthreads(); }
    const float Z1 = rf[0];
    __syncthreads();

    // probs (desc order) and inclusive suffix scan == reference's ascending cumsum
    for (int j = tid; j < NP; j += NT)
        s_a[j] = (j < m) ? __fdiv_rn(expf(s_vals[j] - M), Z1) : 0.f;
    float* src = s_a; float* dst = s_b;
    for (int d = 1; d < NP; d <<= 1) {
        __syncthreads();
        for (int j = tid; j < NP; j += NT)
            dst[j] = src[j] + ((j + d < NP) ? src[j + d] : 0.f);
        float* t = src; src = dst; dst = t;
    }
    __syncthreads();

    // top-p: mask where cum (== suffix) <= 1-p; rank 0 (global max) never masked
    const float c1 = 1.0f - p;
    c = 0;
    for (int j = tid; j < m; j += NT) c += (src[j] > c1) ? 1 : 0;
    ri[tid] = c; __syncthreads();
    for (int s = NT / 2; s; s >>= 1) { if (tid < s) ri[tid] += ri[tid + s]; __syncthreads(); }
    int m2 = ri[0]; if (m2 < 1) m2 = 1;
    __syncthreads();

    // min-p: keep exp(v-M) >= mp (argmax has exp=1, always kept)
    int m3 = m2;
    if (mp > 0.f) {
        c = 0;
        for (int j = tid; j < m2; j += NT) c += (expf(s_vals[j] - M) >= mp) ? 1 : 0;
        ri[tid] = c; __syncthreads();
        for (int s = NT / 2; s; s >>= 1) { if (tid < s) ri[tid] += ri[tid + s]; __syncthreads(); }
        m3 = ri[0]; if (m3 < 1) m3 = 1;
        __syncthreads();
    }

    // ---------------- final: argmax of exp(v-M)/noise over survivors ----------------
    float best = -1.f; int bidx = 0x7FFFFFFF;
    for (int j = tid; j < m3; j += NT) {
        int ix = s_idxs[j];
        float sc = __fdiv_rn(expf(s_vals[j] - M), fmaxf(nz[ix], 1e-10f));
        if (sc > best || (sc == best && ix < bidx)) { best = sc; bidx = ix; }
    }
    rf[tid] = best; ri[tid] = bidx; __syncthreads();
    for (int s = NT / 2; s; s >>= 1) {
        if (tid < s) {
            float ob = rf[tid + s]; int oi = ri[tid + s];
            if (ob > rf[tid] || (ob == rf[tid] && oi < ri[tid])) { rf[tid] = ob; ri[tid] = oi; }
        }
        __syncthreads();
    }
    if (tid == 0) out[row] = (float)ri[0];   // output buffer is float32
}

extern "C" void kernel_launch(void* const* d_in, const int* in_sizes, int n_in,
                              void* d_out, int out_size)
{
    const float* logits = (const float*)d_in[0];
    const float* temps  = (const float*)d_in[1];
    const int*   topks  = (const int*)d_in[2];
    const float* topps  = (const float*)d_in[3];
    const float* minps  = (const float*)d_in[4];
    const float* noise  = (const float*)d_in[5];
    const int B = out_size;              // output: [B] sampled indices
    const int V = in_sizes[0] / B;       // logits: [B, V]

    const size_t smem = (size_t)NC * (4 * sizeof(float));  // vals + idxs + 2 scan bufs
    cudaFuncSetAttribute(sampler_kernel,
                         cudaFuncAttributeMaxDynamicSharedMemorySize, (int)smem);
    sampler_kernel<<<B, NT, smem>>>(logits, temps, topks, topps, minps, noise,
                                    (float*)d_out, V);
}

// round 5
// speedup vs baseline: 3.1385x; 3.1385x over previous
#include <cuda_runtime.h>
#include <math_constants.h>

#define NT 1024      // threads per CTA (one CTA per row)
#define NC 6144      // candidate capacity
#define SP 4096      // survivor / sort / scan capacity
#define HB 2048      // histogram bins over [-16,16), width 1/64

// order-preserving float<->uint (ascending)
__device__ __forceinline__ unsigned f2o(float f) {
    unsigned u = __float_as_uint(f);
    return u ^ ((u & 0x80000000u) ? 0xFFFFFFFFu : 0x80000000u);
}
__device__ __forceinline__ float o2f(unsigned u) {
    unsigned v = u ^ ((u & 0x80000000u) ? 0x80000000u : 0xFFFFFFFFu);
    return __uint_as_float(v);
}
__device__ __forceinline__ int binof(float x) {
    float t = (x + 16.0f) * 64.0f;
    int b = (int)t;
    if (t < 0.f) b = 0;
    if (b > HB - 1) b = HB - 1;
    return b;
}

__device__ __forceinline__ float blk_max(float v, float* w, int tid) {
    #pragma unroll
    for (int o = 16; o; o >>= 1) v = fmaxf(v, __shfl_xor_sync(0xFFFFFFFFu, v, o));
    if ((tid & 31) == 0) w[tid >> 5] = v;
    __syncthreads();
    if (tid < 32) {
        float x = (tid < NT / 32) ? w[tid] : -CUDART_INF_F;
        #pragma unroll
        for (int o = 16; o; o >>= 1) x = fmaxf(x, __shfl_xor_sync(0xFFFFFFFFu, x, o));
        if (tid == 0) w[0] = x;
    }
    __syncthreads();
    float r = w[0];
    __syncthreads();
    return r;
}
__device__ __forceinline__ float blk_sumf(float v, float* w, int tid) {
    #pragma unroll
    for (int o = 16; o; o >>= 1) v += __shfl_xor_sync(0xFFFFFFFFu, v, o);
    if ((tid & 31) == 0) w[tid >> 5] = v;
    __syncthreads();
    if (tid < 32) {
        float x = (tid < NT / 32) ? w[tid] : 0.f;
        #pragma unroll
        for (int o = 16; o; o >>= 1) x += __shfl_xor_sync(0xFFFFFFFFu, x, o);
        if (tid == 0) w[0] = x;
    }
    __syncthreads();
    float r = w[0];
    __syncthreads();
    return r;
}
__device__ __forceinline__ int blk_sumi(int v, int* w, int tid) {
    #pragma unroll
    for (int o = 16; o; o >>= 1) v += __shfl_xor_sync(0xFFFFFFFFu, v, o);
    if ((tid & 31) == 0) w[tid >> 5] = v;
    __syncthreads();
    if (tid < 32) {
        int x = (tid < NT / 32) ? w[tid] : 0;
        #pragma unroll
        for (int o = 16; o; o >>= 1) x += __shfl_xor_sync(0xFFFFFFFFu, x, o);
        if (tid == 0) w[0] = x;
    }
    __syncthreads();
    int r = w[0];
    __syncthreads();
    return r;
}

__global__ __launch_bounds__(NT, 1)
void sampler_kernel(const float* __restrict__ logits,
                    const float* __restrict__ temps,
                    const int*   __restrict__ topks,
                    const float* __restrict__ topps,
                    const float* __restrict__ minps,
                    const float* __restrict__ noise,
                    float* __restrict__ out, int V)
{
    extern __shared__ unsigned char smem_raw[];
    float* s_val  = (float*)smem_raw;            // NC candidate values
    int*   s_idx  = (int*)(s_val + NC);          // NC candidate indices
    float* s_sv   = (float*)(s_idx + NC);        // SP survivor values
    int*   s_si   = (int*)(s_sv + SP);           // SP survivor indices
    float* s_a    = (float*)(s_si + SP);         // SP scan ping (also int scratch)
    float* s_b    = s_a + SP;                    // SP scan pong
    int*   s_hist = (int*)(s_b + SP);            // HB histogram / 256 radix bins

    __shared__ float wf[32];
    __shared__ int   wi[32];
    __shared__ int   sh_cnt, sh_bcut, sh_sel;

    const int tid = threadIdx.x;
    const int row = blockIdx.x;
    const float* lg = logits + (size_t)row * V;
    const float* nz = noise  + (size_t)row * V;
    const float T = temps[row];
    int k = topks[row]; if (k < 1) k = 1; if (k > V) k = V;
    const float p  = topps[row];
    const float mp = minps[row];
    const int lane = tid & 31;
    const unsigned lml = (1u << lane) - 1u;

    // ------- pass 0: max + histogram of x = lg/T, fused -------
    for (int b = tid; b < HB; b += NT) s_hist[b] = 0;
    __syncthreads();

    float lmax = -CUDART_INF_F;
    const float4* lg4 = (const float4*)lg;
    const int V4 = V >> 2;
    for (int i = tid; i < V4; i += NT) {
        float4 v = lg4[i];
        float a = __fdiv_rn(v.x, T), b = __fdiv_rn(v.y, T);
        float c = __fdiv_rn(v.z, T), d = __fdiv_rn(v.w, T);
        lmax = fmaxf(lmax, fmaxf(fmaxf(a, b), fmaxf(c, d)));
        atomicAdd(&s_hist[binof(a)], 1);
        atomicAdd(&s_hist[binof(b)], 1);
        atomicAdd(&s_hist[binof(c)], 1);
        atomicAdd(&s_hist[binof(d)], 1);
    }
    for (int i = (V4 << 2) + tid; i < V; i += NT) {     // tail (V%4)
        float a = __fdiv_rn(lg[i], T);
        lmax = fmaxf(lmax, a);
        atomicAdd(&s_hist[binof(a)], 1);
    }
    const float M = blk_max(lmax, wf, tid);

    // ------- suffix-sum histogram, pick cutoff bin with cum >= k -------
    {
        int* ia = (int*)s_a; int* ib = (int*)s_b;
        for (int b = tid; b < HB; b += NT) ia[b] = s_hist[b];
        __syncthreads();
        for (int d = 1; d < HB; d <<= 1) {
            for (int b = tid; b < HB; b += NT)
                ib[b] = ia[b] + ((b + d < HB) ? ia[b + d] : 0);
            __syncthreads();
            int* t = ia; ia = ib; ib = t;
        }
        for (int b = tid; b < HB; b += NT) {
            int s = ia[b];
            int snext = (b == HB - 1) ? 0 : ia[b + 1];
            if (s >= k && snext < k) sh_bcut = b;
        }
        __syncthreads();
    }
    const int bcut = sh_bcut;

    // ------- gather pass: compact all elements with bin >= bcut -------
    if (tid == 0) sh_cnt = 0;
    __syncthreads();
    {
        const int iters = (V4 + NT - 1) / NT;
        for (int it = 0; it < iters; ++it) {
            int i = tid + it * NT;
            bool in = (i < V4);
            float xs[4] = {0.f, 0.f, 0.f, 0.f};
            if (in) {
                float4 v = lg4[i];
                xs[0] = __fdiv_rn(v.x, T); xs[1] = __fdiv_rn(v.y, T);
                xs[2] = __fdiv_rn(v.z, T); xs[3] = __fdiv_rn(v.w, T);
            }
            #pragma unroll
            for (int c = 0; c < 4; ++c) {
                bool hit = in && (binof(xs[c]) >= bcut);
                unsigned mask = __ballot_sync(0xFFFFFFFFu, hit);
                if (mask) {
                    int leader = __ffs(mask) - 1;
                    int base = 0;
                    if (lane == leader) base = atomicAdd(&sh_cnt, __popc(mask));
                    base = __shfl_sync(0xFFFFFFFFu, base, leader);
                    if (hit) {
                        int pos = base + __popc(mask & lml);
                        if (pos < NC) { s_val[pos] = xs[c]; s_idx[pos] = (i << 2) + c; }
                    }
                }
            }
        }
        for (int i = (V4 << 2) + tid; i < V; i += NT) {   // tail
            float a = __fdiv_rn(lg[i], T);
            if (binof(a) >= bcut) {
                int pos = atomicAdd(&sh_cnt, 1);
                if (pos < NC) { s_val[pos] = a; s_idx[pos] = i; }
            }
        }
    }
    __syncthreads();
    int n = sh_cnt; if (n > NC) n = NC;
    if (k > n) k = n;     // safety (guaranteed n >= k by histogram)
    __syncthreads();

    // ------- exact k-th largest via 4-pass radix select -------
    unsigned prefix = 0;
    int krem = k;
    for (int byte = 3; byte >= 0; --byte) {
        for (int b = tid; b < 256; b += NT) s_hist[b] = 0;
        __syncthreads();
        const unsigned hmask = (byte == 3) ? 0u : (0xFFFFFFFFu << (8 * (byte + 1)));
        for (int j = tid; j < n; j += NT) {
            unsigned u = f2o(s_val[j]);
            if ((u & hmask) == (prefix & hmask))
                atomicAdd(&s_hist[(u >> (8 * byte)) & 255], 1);
        }
        __syncthreads();
        // suffix-sum of 256 bins
        int* ia = (int*)s_a; int* ib = (int*)s_b;
        if (tid < 256) ia[tid] = s_hist[tid];
        __syncthreads();
        for (int d = 1; d < 256; d <<= 1) {
            if (tid < 256) ib[tid] = ia[tid] + ((tid + d < 256) ? ia[tid + d] : 0);
            __syncthreads();
            int* t = ia; ia = ib; ib = t;
        }
        if (tid < 256) {
            int s = ia[tid];
            int snext = (tid == 255) ? 0 : ia[tid + 1];
            if (s >= krem && snext < krem) sh_sel = tid;
        }
        __syncthreads();
        int sel = sh_sel;
        int higher = (sel == 255) ? 0 : ia[sel + 1];
        krem -= higher;
        prefix |= (unsigned)sel << (8 * byte);
        __syncthreads();
    }
    const float thr = o2f(prefix);

    // ------- compact survivors (v >= thr), count m -------
    if (tid == 0) sh_cnt = 0;
    __syncthreads();
    {
        const int iters = (n + NT - 1) / NT;
        for (int it = 0; it < iters; ++it) {
            int j = tid + it * NT;
            bool hit = (j < n) && (s_val[j] >= thr);
            unsigned mask = __ballot_sync(0xFFFFFFFFu, hit);
            if (mask) {
                int leader = __ffs(mask) - 1;
                int base = 0;
                if (lane == leader) base = atomicAdd(&sh_cnt, __popc(mask));
                base = __shfl_sync(0xFFFFFFFFu, base, leader);
                if (hit) {
                    int pos = base + __popc(mask & lml);
                    if (pos < SP) { s_sv[pos] = s_val[j]; s_si[pos] = s_idx[j]; }
                }
            }
        }
    }
    __syncthreads();
    int m = sh_cnt; if (m > SP) m = SP;
    __syncthreads();

    // ------- sort survivors desc by (value, index-desc) -------
    int NP = 1; while (NP < m) NP <<= 1;
    for (int j = m + tid; j < NP; j += NT) { s_sv[j] = -CUDART_INF_F; s_si[j] = -1; }
    __syncthreads();
    for (int size = 2; size <= NP; size <<= 1)
        for (int st = size >> 1; st; st >>= 1) {
            for (int pp = tid; pp < (NP >> 1); pp += NT) {
                int low = pp & (st - 1);
                int i = ((pp ^ low) << 1) | low;
                int l = i + st;
                float vi = s_sv[i], vl = s_sv[l];
                int   ii = s_si[i], il = s_si[l];
                bool dir = ((i & size) == 0);
                bool sw  = (vl > vi) || (vl == vi && il > ii);
                if (sw == dir) { s_sv[i] = vl; s_sv[l] = vi; s_si[i] = il; s_si[l] = ii; }
            }
            __syncthreads();
        }

    // ------- softmax sum over survivors -------
    float z = 0.f;
    for (int j = tid; j < m; j += NT) z += expf(s_sv[j] - M);
    const float Z1 = blk_sumf(z, wf, tid);

    // probs (desc order) + inclusive suffix scan == reference ascending cumsum
    for (int j = tid; j < NP; j += NT)
        s_a[j] = (j < m) ? __fdiv_rn(expf(s_sv[j] - M), Z1) : 0.f;
    float* src = s_a; float* dst = s_b;
    __syncthreads();
    for (int d = 1; d < NP; d <<= 1) {
        for (int j = tid; j < NP; j += NT)
            dst[j] = src[j] + ((j + d < NP) ? src[j + d] : 0.f);
        __syncthreads();
        float* t = src; src = dst; dst = t;
    }

    // top-p: keep cum (== suffix) > 1-p; rank 0 never masked
    const float c1 = 1.0f - p;
    int c = 0;
    for (int j = tid; j < m; j += NT) c += (src[j] > c1) ? 1 : 0;
    int m2 = blk_sumi(c, wi, tid); if (m2 < 1) m2 = 1;

    // min-p: keep exp(v-M) >= mp (argmax exp=1, always kept)
    int m3 = m2;
    if (mp > 0.f) {
        c = 0;
        for (int j = tid; j < m2; j += NT) c += (expf(s_sv[j] - M) >= mp) ? 1 : 0;
        m3 = blk_sumi(c, wi, tid); if (m3 < 1) m3 = 1;
    }

    // ------- final: argmax of exp(v-M)/max(noise,1e-10), min-index ties -------
    float bv = -1.f; int bi = 0x7FFFFFFF;
    for (int j = tid; j < m3; j += NT) {
        int ix = s_si[j];
        float sc = __fdiv_rn(expf(s_sv[j] - M), fmaxf(nz[ix], 1e-10f));
        if (sc > bv || (sc == bv && ix < bi)) { bv = sc; bi = ix; }
    }
    #pragma unroll
    for (int o = 16; o; o >>= 1) {
        float ov = __shfl_xor_sync(0xFFFFFFFFu, bv, o);
        int   oi = __shfl_xor_sync(0xFFFFFFFFu, bi, o);
        if (ov > bv || (ov == bv && oi < bi)) { bv = ov; bi = oi; }
    }
    if (lane == 0) { wf[tid >> 5] = bv; wi[tid >> 5] = bi; }
    __syncthreads();
    if (tid < 32) {
        float xv = (tid < NT / 32) ? wf[tid] : -1.f;
        int   xi = (tid < NT / 32) ? wi[tid] : 0x7FFFFFFF;
        #pragma unroll
        for (int o = 16; o; o >>= 1) {
            float ov = __shfl_xor_sync(0xFFFFFFFFu, xv, o);
            int   oi = __shfl_xor_sync(0xFFFFFFFFu, xi, o);
            if (ov > xv || (ov == xv && oi < xi)) { xv = ov; xi = oi; }
        }
        if (tid == 0) out[row] = (float)xi;
    }
}

extern "C" void kernel_launch(void* const* d_in, const int* in_sizes, int n_in,
                              void* d_out, int out_size)
{
    const float* logits = (const float*)d_in[0];
    const float* temps  = (const float*)d_in[1];
    const int*   topks  = (const int*)d_in[2];
    const float* topps  = (const float*)d_in[3];
    const float* minps  = (const float*)d_in[4];
    const float* noise  = (const float*)d_in[5];
    const int B = out_size;              // output: [B] sampled indices (float32)
    const int V = in_sizes[0] / B;       // logits: [B, V]

    const size_t smem = (size_t)NC * 8 + (size_t)SP * 8 + (size_t)SP * 8 + (size_t)HB * 4;
    cudaFuncSetAttribute(sampler_kernel,
                         cudaFuncAttributeMaxDynamicSharedMemorySize, (int)smem);
    sampler_kernel<<<B, NT, smem>>>(logits, temps, topks, topps, minps, noise,
                                    (float*)d_out, V);
}